// round 2
// baseline (speedup 1.0000x reference)
#include <cuda_runtime.h>
#include <math.h>

#define NN 100000
#define NE 1600000
#define NG 64
#define F1 100
#define F2 200

// ---------------- scratch (static device globals; no allocation) ----------
__device__ float g_dinv[NN];          // deg -> dinv (in place)
__device__ float g_norm[NE];          // per-edge normalization
__device__ float g_aggX[NN * 3];      // A_norm @ x
__device__ float g_h1[NN * F1];       // silu(aggX @ W1 + b1)
__device__ float g_agg1[NN * F1];     // A_norm @ h1
__device__ float g_h2[NN * F2];       // silu(agg1 @ W2 + b2)
__device__ float g_sums[NG * F2];     // pooled sums
__device__ float g_cnt[NG];           // pooled counts

__device__ __forceinline__ float silu(float v) {
    return v / (1.0f + __expf(-v));
}

__device__ __forceinline__ void red_add_v4(float* p, float4 v) {
#if __CUDA_ARCH__ >= 900
    asm volatile("red.global.add.v4.f32 [%0], {%1,%2,%3,%4};"
                 :: "l"(p), "f"(v.x), "f"(v.y), "f"(v.z), "f"(v.w) : "memory");
#else
    atomicAdd(p + 0, v.x); atomicAdd(p + 1, v.y);
    atomicAdd(p + 2, v.z); atomicAdd(p + 3, v.w);
#endif
}

// ---------------- K1: init deg (self-loop weight 1), zero pooled ----------
__global__ void k_init() {
    int i = blockIdx.x * blockDim.x + threadIdx.x;
    if (i < NN) g_dinv[i] = 1.0f;          // self-loop contributes 1 to deg
    if (i < NG * F2) g_sums[i] = 0.0f;
    if (i < NG) g_cnt[i] = 0.0f;
}

// ---------------- K2: deg[col] += w ---------------------------------------
__global__ void k_deg(const int* __restrict__ ei, const float* __restrict__ w) {
    int e = blockIdx.x * blockDim.x + threadIdx.x;
    if (e < NE) atomicAdd(&g_dinv[ei[NE + e]], w[e]);
}

// ---------------- K3: dinv = rsqrt(deg); aggX self-loop init --------------
__global__ void k_dinv(const float* __restrict__ x) {
    int i = blockIdx.x * blockDim.x + threadIdx.x;
    if (i >= NN) return;
    float d = g_dinv[i];
    float di = (d > 0.0f) ? rsqrtf(d) : 0.0f;
    g_dinv[i] = di;
    float s = di * di;               // self-loop norm: dinv*1*dinv
    g_aggX[3 * i + 0] = s * x[3 * i + 0];
    g_aggX[3 * i + 1] = s * x[3 * i + 1];
    g_aggX[3 * i + 2] = s * x[3 * i + 2];
}

// ---------------- K4: norm[e]; scatter x (3 floats/edge) ------------------
__global__ void k_scatterX(const int* __restrict__ ei, const float* __restrict__ w,
                           const float* __restrict__ x) {
    int e = blockIdx.x * blockDim.x + threadIdx.x;
    if (e >= NE) return;
    int row = ei[e];
    int col = ei[NE + e];
    float nm = g_dinv[row] * w[e] * g_dinv[col];
    g_norm[e] = nm;
    atomicAdd(&g_aggX[3 * col + 0], nm * x[3 * row + 0]);
    atomicAdd(&g_aggX[3 * col + 1], nm * x[3 * row + 1]);
    atomicAdd(&g_aggX[3 * col + 2], nm * x[3 * row + 2]);
}

// ---------------- K5: h1 = silu(aggX@W1 + b1); agg1 self-loop init --------
__global__ void k_h1(const float* __restrict__ W1, const float* __restrict__ b1) {
    __shared__ float sW[4 * F1];   // W1 (3x100) then b1 (100)
    for (int t = threadIdx.x; t < 4 * F1; t += blockDim.x)
        sW[t] = (t < 3 * F1) ? W1[t] : b1[t - 3 * F1];
    __syncthreads();
    int idx = blockIdx.x * blockDim.x + threadIdx.x;
    if (idx >= NN * 25) return;
    int n = idx / 25, c4 = idx % 25;
    float a0 = g_aggX[3 * n + 0];
    float a1 = g_aggX[3 * n + 1];
    float a2 = g_aggX[3 * n + 2];
    float di = g_dinv[n];
    float s = di * di;
#pragma unroll
    for (int j = 0; j < 4; j++) {
        int c = c4 * 4 + j;
        float v = fmaf(a0, sW[c], fmaf(a1, sW[F1 + c], fmaf(a2, sW[2 * F1 + c], sW[3 * F1 + c])));
        v = silu(v);
        g_h1[n * F1 + c] = v;
        g_agg1[n * F1 + c] = s * v;     // self-loop term of layer-2 aggregation
    }
}

// ---------------- K6: scatter h1 (100 floats/edge, v4 red) ----------------
__global__ void k_scatter1(const int* __restrict__ ei) {
    int idx = blockIdx.x * blockDim.x + threadIdx.x;
    if (idx >= NE * 25) return;
    int e = idx / 25, c = idx % 25;
    int row = ei[e];
    int col = ei[NE + e];
    float nm = g_norm[e];
    float4 hv = *(const float4*)(g_h1 + row * F1 + c * 4);
    float4 m;
    m.x = nm * hv.x; m.y = nm * hv.y; m.z = nm * hv.z; m.w = nm * hv.w;
    red_add_v4(g_agg1 + col * F1 + c * 4, m);
}

// ---------------- K7: h2 = silu(agg1 @ W2 + b2)  (SGEMM) ------------------
// BM=64 nodes, BN=40 cols, 160 threads, 4x4 micro-tile, K=100 fully staged.
#define BM 64
#define BN 40
#define AS_STRIDE 128   // floats per m-row (32 float4 chunks; allows 5-bit xor swizzle)

__global__ void k_gemm2(const float* __restrict__ W2, const float* __restrict__ b2) {
    __shared__ float As[BM * AS_STRIDE];   // [m][k], f4-chunk xor-swizzled
    __shared__ float Bs[F1 * BN];          // [k][c]
    int tid = threadIdx.x;
    int n0 = blockIdx.x * BM;
    int cb = blockIdx.y * BN;

    // load A tile (coalesced along k; swizzled f4 store)
    for (int t = tid; t < BM * 25; t += 160) {
        int m = t / 25, k4 = t % 25;
        int n = n0 + m;
        float4 v = make_float4(0.f, 0.f, 0.f, 0.f);
        if (n < NN) v = *(const float4*)(g_agg1 + n * F1 + k4 * 4);
        int chunk = k4 ^ ((m >> 2) & 7);
        *(float4*)(As + m * AS_STRIDE + chunk * 4) = v;
    }
    // load B tile
    for (int t = tid; t < F1 * 10; t += 160) {
        int k = t / 10, c4 = t % 10;
        *(float4*)(Bs + k * BN + c4 * 4) = *(const float4*)(W2 + k * F2 + cb + c4 * 4);
    }
    __syncthreads();

    int tidx = tid % 10;  // col group
    int tidy = tid / 10;  // row group (0..15)
    float acc[4][4] = {};

#pragma unroll 5
    for (int k4 = 0; k4 < 25; k4++) {
        float4 a[4];
        int chunk = (k4 ^ (tidy & 7)) << 2;
#pragma unroll
        for (int i = 0; i < 4; i++) {
            int m = tidy * 4 + i;
            a[i] = *(const float4*)(As + m * AS_STRIDE + chunk);
        }
#pragma unroll
        for (int kk = 0; kk < 4; kk++) {
            float4 bv = *(const float4*)(Bs + (k4 * 4 + kk) * BN + tidx * 4);
#pragma unroll
            for (int i = 0; i < 4; i++) {
                float av = (&a[i].x)[kk];
                acc[i][0] = fmaf(av, bv.x, acc[i][0]);
                acc[i][1] = fmaf(av, bv.y, acc[i][1]);
                acc[i][2] = fmaf(av, bv.z, acc[i][2]);
                acc[i][3] = fmaf(av, bv.w, acc[i][3]);
            }
        }
    }

    int cbase = cb + tidx * 4;
    float4 bias = *(const float4*)(b2 + cbase);
#pragma unroll
    for (int i = 0; i < 4; i++) {
        int n = n0 + tidy * 4 + i;
        if (n < NN) {
            float4 o;
            o.x = silu(acc[i][0] + bias.x);
            o.y = silu(acc[i][1] + bias.y);
            o.z = silu(acc[i][2] + bias.z);
            o.w = silu(acc[i][3] + bias.w);
            *(float4*)(g_h2 + n * F2 + cbase) = o;
        }
    }
}

// ---------------- K8: segmented mean-pool (batch is sorted) ---------------
#define PN 512
__global__ void k_pool(const int* __restrict__ batch) {
    int c = threadIdx.x;        // 0..255; 0..199 handle cols, 200 handles counts
    int n0 = blockIdx.x * PN;
    int nend = min(n0 + PN, NN);
    if (c < F2) {
        float acc = 0.f; int curg = -1;
        for (int n = n0; n < nend; n++) {
            int g = batch[n];
            if (g != curg) {
                if (curg >= 0) atomicAdd(&g_sums[curg * F2 + c], acc);
                curg = g; acc = 0.f;
            }
            acc += g_h2[n * F2 + c];
        }
        if (curg >= 0) atomicAdd(&g_sums[curg * F2 + c], acc);
    } else if (c == F2) {
        float cnt = 0.f; int curg = -1;
        for (int n = n0; n < nend; n++) {
            int g = batch[n];
            if (g != curg) {
                if (curg >= 0) atomicAdd(&g_cnt[curg], cnt);
                curg = g; cnt = 0.f;
            }
            cnt += 1.0f;
        }
        if (curg >= 0) atomicAdd(&g_cnt[curg], cnt);
    }
}

// ---------------- K9: head: silu(pooled@Wl1+bl1)@Wl2+bl2 ------------------
__global__ void k_head(const float* __restrict__ Wl1, const float* __restrict__ bl1,
                       const float* __restrict__ Wl2, const float* __restrict__ bl2,
                       float* __restrict__ out) {
    __shared__ float sp[F2];
    __shared__ float sh[F1];
    int g = blockIdx.x;
    int tid = threadIdx.x;
    float cnt = fmaxf(g_cnt[g], 1.0f);
    for (int c = tid; c < F2; c += blockDim.x)
        sp[c] = g_sums[g * F2 + c] / cnt;
    __syncthreads();
    if (tid < F1) {
        float acc = bl1[tid];
        for (int c = 0; c < F2; c++)
            acc = fmaf(sp[c], Wl1[c * F1 + tid], acc);
        sh[tid] = silu(acc);
    }
    __syncthreads();
    if (tid == 0) {
        float s = bl2[0];
        for (int j = 0; j < F1; j++)
            s = fmaf(sh[j], Wl2[j], s);
        out[g] = s;
    }
}

// ---------------- launch ---------------------------------------------------
extern "C" void kernel_launch(void* const* d_in, const int* in_sizes, int n_in,
                              void* d_out, int out_size) {
    const float* x   = (const float*)d_in[0];
    const float* ea  = (const float*)d_in[1];
    const float* W1  = (const float*)d_in[2];
    const float* b1  = (const float*)d_in[3];
    const float* W2  = (const float*)d_in[4];
    const float* b2  = (const float*)d_in[5];
    const float* Wl1 = (const float*)d_in[6];
    const float* bl1 = (const float*)d_in[7];
    const float* Wl2 = (const float*)d_in[8];
    const float* bl2 = (const float*)d_in[9];
    const int*   ei  = (const int*)d_in[10];
    const int*   bat = (const int*)d_in[11];
    float* out = (float*)d_out;

    k_init<<<(NN + 255) / 256, 256>>>();
    k_deg<<<(NE + 255) / 256, 256>>>(ei, ea);
    k_dinv<<<(NN + 255) / 256, 256>>>(x);
    k_scatterX<<<(NE + 255) / 256, 256>>>(ei, ea, x);
    k_h1<<<(NN * 25 + 255) / 256, 256>>>(W1, b1);
    k_scatter1<<<(NE * 25 + 255) / 256, 256>>>(ei);
    k_gemm2<<<dim3((NN + BM - 1) / BM, F2 / BN), 160>>>(W2, b2);
    k_pool<<<(NN + PN - 1) / PN, 256>>>(bat);
    k_head<<<NG, 128>>>(Wl1, bl1, Wl2, bl2, out);
}

// round 3
// speedup vs baseline: 1.8578x; 1.8578x over previous
#include <cuda_runtime.h>
#include <math.h>

#define NN 100000
#define NE 1600000
#define NG 64
#define F1 100
#define F2 200

// ---------------- scratch (static device globals; no allocation) ----------
__device__ float  g_dinv[NN];          // deg -> dinv (in place)
__device__ int    g_cdeg[NN];          // in-degree counts (for CSR)
__device__ int    g_offs[NN + 1];      // CSR offsets
__device__ int    g_fill[NN];          // CSR fill cursors
__device__ int    g_bsum[128];         // scan block sums
__device__ float2 g_csr[NE];           // (row as int bits, norm)
__device__ float  g_aggX[NN * 3];      // A_norm @ x
__device__ float  g_h1[NN * F1];       // silu(aggX @ W1 + b1)
__device__ float  g_agg1[NN * F1];     // A_norm @ h1
__device__ float  g_sums[NG * F2];     // pooled sums
__device__ float  g_cnt[NG];           // pooled counts

__device__ __forceinline__ float silu(float v) {
    return v / (1.0f + __expf(-v));
}

// ---------------- K1: init deg (self-loop weight 1), zero counts/pooled ---
__global__ void k_init() {
    int i = blockIdx.x * blockDim.x + threadIdx.x;
    if (i < NN) { g_dinv[i] = 1.0f; g_cdeg[i] = 0; }
    if (i < NG * F2) g_sums[i] = 0.0f;
    if (i < NG) g_cnt[i] = 0.0f;
}

// ---------------- K2: deg[col] += w; cdeg[col]++ ---------------------------
__global__ void k_deg(const int* __restrict__ ei, const float* __restrict__ w) {
    int e = blockIdx.x * blockDim.x + threadIdx.x;
    if (e >= NE) return;
    int col = ei[NE + e];
    atomicAdd(&g_dinv[col], w[e]);
    atomicAdd(&g_cdeg[col], 1);
}

// ---------------- K3: dinv = rsqrt(deg); warp-aggregated graph counts -----
__global__ void k_dinv(const int* __restrict__ batch) {
    int n = blockIdx.x * blockDim.x + threadIdx.x;
    bool valid = n < NN;
    if (valid) g_dinv[n] = rsqrtf(g_dinv[n]);   // deg >= 1 (self loop)
    int g = valid ? batch[n] : -1;
    unsigned m = __match_any_sync(0xffffffffu, g);
    int lane = threadIdx.x & 31;
    int leader = __ffs(m) - 1;
    if (valid && lane == leader)
        atomicAdd(&g_cnt[g], (float)__popc(m));
}

// ---------------- scan: exclusive prefix sum of cdeg -> offs --------------
// K4a: per-block (1024 elems) local exclusive scan + block sums
__global__ void k_scan1() {
    __shared__ int warp_s[8];
    int b = blockIdx.x, t = threadIdx.x;
    int base = b * 1024 + t * 4;
    int v0 = 0, v1 = 0, v2 = 0, v3 = 0;
    if (base + 0 < NN) v0 = g_cdeg[base + 0];
    if (base + 1 < NN) v1 = g_cdeg[base + 1];
    if (base + 2 < NN) v2 = g_cdeg[base + 2];
    if (base + 3 < NN) v3 = g_cdeg[base + 3];
    int s = v0 + v1 + v2 + v3;
    int lane = t & 31, wid = t >> 5;
    int ps = s;
#pragma unroll
    for (int o = 1; o < 32; o <<= 1) {
        int u = __shfl_up_sync(0xffffffffu, ps, o);
        if (lane >= o) ps += u;
    }
    if (lane == 31) warp_s[wid] = ps;
    __syncthreads();
    if (t < 8) {
        int ws = warp_s[t];
        int pw = ws;
#pragma unroll
        for (int o = 1; o < 8; o <<= 1) {
            int u = __shfl_up_sync(0xffu, pw, o);
            if (t >= o) pw += u;
        }
        warp_s[t] = pw - ws;    // exclusive warp prefix
    }
    __syncthreads();
    int ex = ps - s + warp_s[wid];   // exclusive prefix of this thread
    int run = ex;
    if (base + 0 < NN) g_offs[base + 0] = run; run += v0;
    if (base + 1 < NN) g_offs[base + 1] = run; run += v1;
    if (base + 2 < NN) g_offs[base + 2] = run; run += v2;
    if (base + 3 < NN) g_offs[base + 3] = run;
    if (t == 255) g_bsum[b] = ex + s;
}

// K4b: scan the (<=98) block sums
__global__ void k_scan2() {
    __shared__ int sh[4];
    int t = threadIdx.x;
    int v = (t < 98) ? g_bsum[t] : 0;
    int lane = t & 31, wid = t >> 5;
    int ps = v;
#pragma unroll
    for (int o = 1; o < 32; o <<= 1) {
        int u = __shfl_up_sync(0xffffffffu, ps, o);
        if (lane >= o) ps += u;
    }
    if (lane == 31) sh[wid] = ps;
    __syncthreads();
    if (t < 4) {
        int ws = sh[t];
        int pw = ws;
#pragma unroll
        for (int o = 1; o < 4; o <<= 1) {
            int u = __shfl_up_sync(0xfu, pw, o);
            if (t >= o) pw += u;
        }
        sh[t] = pw - ws;
    }
    __syncthreads();
    if (t < 98) g_bsum[t] = ps - v + sh[wid];
}

// K4c: add block offsets; init fill cursors; offs[NN] = NE
__global__ void k_scan3() {
    int i = blockIdx.x * blockDim.x + threadIdx.x;
    if (i < NN) {
        int o = g_offs[i] + g_bsum[i >> 10];
        g_offs[i] = o;
        g_fill[i] = o;
    }
    if (i == 0) g_offs[NN] = NE;
}

// ---------------- K5: build CSR (row, norm) per target node ---------------
__global__ void k_build(const int* __restrict__ ei, const float* __restrict__ w) {
    int e = blockIdx.x * blockDim.x + threadIdx.x;
    if (e >= NE) return;
    int row = ei[e];
    int col = ei[NE + e];
    float nm = g_dinv[row] * w[e] * g_dinv[col];
    int pos = atomicAdd(&g_fill[col], 1);
    g_csr[pos] = make_float2(__int_as_float(row), nm);
}

// ---------------- K6: aggX[n] = s*x[n] + sum nrm*x[row]  (gather) ---------
__global__ void k_aggX(const float* __restrict__ x) {
    int n = blockIdx.x * blockDim.x + threadIdx.x;
    if (n >= NN) return;
    float di = g_dinv[n];
    float s = di * di;
    float a0 = s * x[3 * n + 0];
    float a1 = s * x[3 * n + 1];
    float a2 = s * x[3 * n + 2];
    int beg = g_offs[n], end = g_offs[n + 1];
    for (int j = beg; j < end; j++) {
        float2 c = g_csr[j];
        int r = __float_as_int(c.x);
        float nm = c.y;
        a0 = fmaf(nm, x[3 * r + 0], a0);
        a1 = fmaf(nm, x[3 * r + 1], a1);
        a2 = fmaf(nm, x[3 * r + 2], a2);
    }
    g_aggX[3 * n + 0] = a0;
    g_aggX[3 * n + 1] = a1;
    g_aggX[3 * n + 2] = a2;
}

// ---------------- K7: h1 = silu(aggX @ W1 + b1) ---------------------------
__global__ void k_h1(const float* __restrict__ W1, const float* __restrict__ b1) {
    __shared__ float sW[4 * F1];   // W1 (3x100) then b1 (100)
    for (int t = threadIdx.x; t < 4 * F1; t += blockDim.x)
        sW[t] = (t < 3 * F1) ? W1[t] : b1[t - 3 * F1];
    __syncthreads();
    int idx = blockIdx.x * blockDim.x + threadIdx.x;
    if (idx >= NN * 25) return;
    int n = idx / 25, c4 = idx % 25;
    float a0 = g_aggX[3 * n + 0];
    float a1 = g_aggX[3 * n + 1];
    float a2 = g_aggX[3 * n + 2];
#pragma unroll
    for (int j = 0; j < 4; j++) {
        int c = c4 * 4 + j;
        float v = fmaf(a0, sW[c], fmaf(a1, sW[F1 + c], fmaf(a2, sW[2 * F1 + c], sW[3 * F1 + c])));
        g_h1[n * F1 + c] = silu(v);
    }
}

// ---------------- K8: agg1[n] = s*h1[n] + sum nrm*h1[row] (warp/node) -----
__global__ void k_agg1() {
    int n = (blockIdx.x * blockDim.x + threadIdx.x) >> 5;
    int lane = threadIdx.x & 31;
    if (n >= NN) return;
    bool act = lane < 25;
    int beg = g_offs[n], end = g_offs[n + 1];
    float di = g_dinv[n];
    float s = di * di;
    float4 acc = make_float4(0.f, 0.f, 0.f, 0.f);
    if (act) {
        float4 h = *(const float4*)(g_h1 + (long)n * F1 + lane * 4);
        acc.x = s * h.x; acc.y = s * h.y; acc.z = s * h.z; acc.w = s * h.w;
    }
    int j = beg;
    for (; j + 2 <= end; j += 2) {
        float2 c0 = g_csr[j];
        float2 c1 = g_csr[j + 1];
        int r0 = __float_as_int(c0.x);
        int r1 = __float_as_int(c1.x);
        if (act) {
            float4 h0 = *(const float4*)(g_h1 + (long)r0 * F1 + lane * 4);
            float4 h1v = *(const float4*)(g_h1 + (long)r1 * F1 + lane * 4);
            acc.x = fmaf(c0.y, h0.x, acc.x); acc.y = fmaf(c0.y, h0.y, acc.y);
            acc.z = fmaf(c0.y, h0.z, acc.z); acc.w = fmaf(c0.y, h0.w, acc.w);
            acc.x = fmaf(c1.y, h1v.x, acc.x); acc.y = fmaf(c1.y, h1v.y, acc.y);
            acc.z = fmaf(c1.y, h1v.z, acc.z); acc.w = fmaf(c1.y, h1v.w, acc.w);
        }
    }
    if (j < end) {
        float2 c0 = g_csr[j];
        int r0 = __float_as_int(c0.x);
        if (act) {
            float4 h0 = *(const float4*)(g_h1 + (long)r0 * F1 + lane * 4);
            acc.x = fmaf(c0.y, h0.x, acc.x); acc.y = fmaf(c0.y, h0.y, acc.y);
            acc.z = fmaf(c0.y, h0.z, acc.z); acc.w = fmaf(c0.y, h0.w, acc.w);
        }
    }
    if (act)
        *(float4*)(g_agg1 + (long)n * F1 + lane * 4) = acc;
}

// ---------------- K9: SGEMM + silu + fused mean-pool sums -----------------
// BM=64 nodes, BN=40 cols, 160 threads, 4x4 micro-tile, K=100 fully staged.
#define BM 64
#define BN 40
#define AS_STRIDE 128   // floats per m-row (32 float4 chunks; 5-bit xor swizzle)

__global__ void k_gemm2(const float* __restrict__ W2, const float* __restrict__ b2,
                        const int* __restrict__ batch) {
    __shared__ float As[BM * AS_STRIDE];   // [m][k], f4-chunk xor-swizzled; reused as sOut
    __shared__ float Bs[F1 * BN];          // [k][c]
    __shared__ int sBatch[BM];
    int tid = threadIdx.x;
    int n0 = blockIdx.x * BM;
    int cb = blockIdx.y * BN;

    // load A tile (coalesced along k; swizzled f4 store)
    for (int t = tid; t < BM * 25; t += 160) {
        int m = t / 25, k4 = t % 25;
        int n = n0 + m;
        float4 v = make_float4(0.f, 0.f, 0.f, 0.f);
        if (n < NN) v = *(const float4*)(g_agg1 + (long)n * F1 + k4 * 4);
        int chunk = k4 ^ ((m >> 2) & 7);
        *(float4*)(As + m * AS_STRIDE + chunk * 4) = v;
    }
    // load B tile
    for (int t = tid; t < F1 * 10; t += 160) {
        int k = t / 10, c4 = t % 10;
        *(float4*)(Bs + k * BN + c4 * 4) = *(const float4*)(W2 + k * F2 + cb + c4 * 4);
    }
    if (tid < BM) {
        int n = n0 + tid;
        sBatch[tid] = (n < NN) ? batch[n] : -1;
    }
    __syncthreads();

    int tidx = tid % 10;  // col group
    int tidy = tid / 10;  // row group (0..15)
    float acc[4][4] = {};

#pragma unroll 5
    for (int k4 = 0; k4 < 25; k4++) {
        float4 a[4];
        int chunk = (k4 ^ (tidy & 7)) << 2;
#pragma unroll
        for (int i = 0; i < 4; i++) {
            int m = tidy * 4 + i;
            a[i] = *(const float4*)(As + m * AS_STRIDE + chunk);
        }
#pragma unroll
        for (int kk = 0; kk < 4; kk++) {
            float4 bv = *(const float4*)(Bs + (k4 * 4 + kk) * BN + tidx * 4);
#pragma unroll
            for (int i = 0; i < 4; i++) {
                float av = (&a[i].x)[kk];
                acc[i][0] = fmaf(av, bv.x, acc[i][0]);
                acc[i][1] = fmaf(av, bv.y, acc[i][1]);
                acc[i][2] = fmaf(av, bv.z, acc[i][2]);
                acc[i][3] = fmaf(av, bv.w, acc[i][3]);
            }
        }
    }

    // epilogue: silu(acc+bias) -> smem; segmented pool -> g_sums
    __syncthreads();               // done reading As/Bs
    float* sOut = As;              // reuse: [BM][BN]
    int cbase = cb + tidx * 4;
    float4 bias = *(const float4*)(b2 + cbase);
#pragma unroll
    for (int i = 0; i < 4; i++) {
        int m = tidy * 4 + i;
        sOut[m * BN + tidx * 4 + 0] = silu(acc[i][0] + bias.x);
        sOut[m * BN + tidx * 4 + 1] = silu(acc[i][1] + bias.y);
        sOut[m * BN + tidx * 4 + 2] = silu(acc[i][2] + bias.z);
        sOut[m * BN + tidx * 4 + 3] = silu(acc[i][3] + bias.w);
    }
    __syncthreads();

    int c = tid % BN;          // 0..39
    int seg = tid / BN;        // 0..3, rows seg*16 .. seg*16+15
    float pacc = 0.f;
    int curg = -1;
    for (int m = seg * 16; m < seg * 16 + 16; m++) {
        int g = sBatch[m];
        if (g != curg) {
            if (curg >= 0) atomicAdd(&g_sums[curg * F2 + cb + c], pacc);
            curg = g;
            pacc = 0.f;
        }
        if (g >= 0) pacc += sOut[m * BN + c];
    }
    if (curg >= 0) atomicAdd(&g_sums[curg * F2 + cb + c], pacc);
}

// ---------------- K10: head: silu(pooled@Wl1+bl1)@Wl2+bl2 -----------------
__global__ void k_head(const float* __restrict__ Wl1, const float* __restrict__ bl1,
                       const float* __restrict__ Wl2, const float* __restrict__ bl2,
                       float* __restrict__ out) {
    __shared__ float sp[F2];
    __shared__ float sh[F1];
    int g = blockIdx.x;
    int tid = threadIdx.x;
    float cnt = fmaxf(g_cnt[g], 1.0f);
    for (int c = tid; c < F2; c += blockDim.x)
        sp[c] = g_sums[g * F2 + c] / cnt;
    __syncthreads();
    if (tid < F1) {
        float acc = bl1[tid];
        for (int c = 0; c < F2; c++)
            acc = fmaf(sp[c], Wl1[c * F1 + tid], acc);
        sh[tid] = silu(acc);
    }
    __syncthreads();
    if (tid == 0) {
        float s = bl2[0];
        for (int j = 0; j < F1; j++)
            s = fmaf(sh[j], Wl2[j], s);
        out[g] = s;
    }
}

// ---------------- launch ---------------------------------------------------
extern "C" void kernel_launch(void* const* d_in, const int* in_sizes, int n_in,
                              void* d_out, int out_size) {
    const float* x   = (const float*)d_in[0];
    const float* ea  = (const float*)d_in[1];
    const float* W1  = (const float*)d_in[2];
    const float* b1  = (const float*)d_in[3];
    const float* W2  = (const float*)d_in[4];
    const float* b2  = (const float*)d_in[5];
    const float* Wl1 = (const float*)d_in[6];
    const float* bl1 = (const float*)d_in[7];
    const float* Wl2 = (const float*)d_in[8];
    const float* bl2 = (const float*)d_in[9];
    const int*   ei  = (const int*)d_in[10];
    const int*   bat = (const int*)d_in[11];
    float* out = (float*)d_out;

    k_init<<<(NN + 255) / 256, 256>>>();
    k_deg<<<(NE + 255) / 256, 256>>>(ei, ea);
    k_dinv<<<(NN + 255) / 256, 256>>>(bat);
    k_scan1<<<98, 256>>>();
    k_scan2<<<1, 128>>>();
    k_scan3<<<(NN + 255) / 256, 256>>>();
    k_build<<<(NE + 255) / 256, 256>>>(ei, ea);
    k_aggX<<<(NN + 255) / 256, 256>>>(x);
    k_h1<<<(NN * 25 + 255) / 256, 256>>>(W1, b1);
    k_agg1<<<(NN * 32 + 255) / 256, 256>>>();
    k_gemm2<<<dim3((NN + BM - 1) / BM, F2 / BN), 160>>>(W2, b2, bat);
    k_head<<<NG, 128>>>(Wl1, bl1, Wl2, bl2, out);
}

// round 5
// speedup vs baseline: 2.0907x; 1.1254x over previous
#include <cuda_runtime.h>
#include <math.h>

#define NN 100000
#define NE 1600000
#define NG 64
#define F1 100
#define F2 200

// ---------------- scratch (static device globals; no allocation) ----------
__device__ float  g_dinv[NN];          // deg -> dinv (in place)
__device__ int    g_cdeg[NN];          // in-degree counts (for CSR)
__device__ int    g_offs[NN + 1];      // CSR offsets
__device__ int    g_fill[NN];          // CSR fill cursors
__device__ int    g_bsum[128];         // scan block sums
__device__ float2 g_csr[NE];           // (row as int bits, norm)
__device__ float  g_aggX[NN * 3];      // A_norm @ x
__device__ float  g_h1[NN * F1];       // silu(aggX @ W1 + b1)
__device__ float  g_agg1[NN * F1];     // A_norm @ h1
__device__ float  g_sums[NG * F2];     // pooled sums
__device__ float  g_cnt[NG];           // pooled counts

__device__ __forceinline__ float silu(float v) {
    return v / (1.0f + __expf(-v));
}

__device__ __forceinline__ unsigned f2tf32(float v) {
    unsigned r;
    asm("cvt.rna.tf32.f32 %0, %1;" : "=r"(r) : "f"(v));
    return r;
}

// split v into tf32 hi + tf32 lo (3xTF32 emulation; lo*lo term dropped)
__device__ __forceinline__ void split_tf32(float v, unsigned& hi, unsigned& lo) {
    hi = f2tf32(v);
    lo = f2tf32(v - __uint_as_float(hi));
}

__device__ __forceinline__ void mma_tf32(float& d0, float& d1, float& d2, float& d3,
                                         unsigned a0, unsigned a1, unsigned a2, unsigned a3,
                                         unsigned b0, unsigned b1) {
    asm volatile("mma.sync.aligned.m16n8k8.row.col.f32.tf32.tf32.f32 "
                 "{%0,%1,%2,%3}, {%4,%5,%6,%7}, {%8,%9}, {%0,%1,%2,%3};"
                 : "+f"(d0), "+f"(d1), "+f"(d2), "+f"(d3)
                 : "r"(a0), "r"(a1), "r"(a2), "r"(a3), "r"(b0), "r"(b1));
}

// ---------------- K1: init deg (self-loop weight 1), zero counts/pooled ---
__global__ void k_init() {
    int i = blockIdx.x * blockDim.x + threadIdx.x;
    if (i < NN) { g_dinv[i] = 1.0f; g_cdeg[i] = 0; }
    if (i < NG * F2) g_sums[i] = 0.0f;
    if (i < NG) g_cnt[i] = 0.0f;
}

// ---------------- K2: deg[col] += w; cdeg[col]++ ---------------------------
__global__ void k_deg(const int* __restrict__ ei, const float* __restrict__ w) {
    int e = blockIdx.x * blockDim.x + threadIdx.x;
    if (e >= NE) return;
    int col = ei[NE + e];
    atomicAdd(&g_dinv[col], w[e]);
    atomicAdd(&g_cdeg[col], 1);
}

// ---------------- K3: dinv = rsqrt(deg); warp-aggregated graph counts -----
__global__ void k_dinv(const int* __restrict__ batch) {
    int n = blockIdx.x * blockDim.x + threadIdx.x;
    bool valid = n < NN;
    if (valid) g_dinv[n] = rsqrtf(g_dinv[n]);   // deg >= 1 (self loop)
    int g = valid ? batch[n] : -1;
    unsigned m = __match_any_sync(0xffffffffu, g);
    int lane = threadIdx.x & 31;
    int leader = __ffs(m) - 1;
    if (valid && lane == leader)
        atomicAdd(&g_cnt[g], (float)__popc(m));
}

// ---------------- scan: exclusive prefix sum of cdeg -> offs --------------
__global__ void k_scan1() {
    __shared__ int warp_s[8];
    int b = blockIdx.x, t = threadIdx.x;
    int base = b * 1024 + t * 4;
    int v0 = 0, v1 = 0, v2 = 0, v3 = 0;
    if (base + 0 < NN) v0 = g_cdeg[base + 0];
    if (base + 1 < NN) v1 = g_cdeg[base + 1];
    if (base + 2 < NN) v2 = g_cdeg[base + 2];
    if (base + 3 < NN) v3 = g_cdeg[base + 3];
    int s = v0 + v1 + v2 + v3;
    int lane = t & 31, wid = t >> 5;
    int ps = s;
#pragma unroll
    for (int o = 1; o < 32; o <<= 1) {
        int u = __shfl_up_sync(0xffffffffu, ps, o);
        if (lane >= o) ps += u;
    }
    if (lane == 31) warp_s[wid] = ps;
    __syncthreads();
    if (t < 8) {
        int ws = warp_s[t];
        int pw = ws;
#pragma unroll
        for (int o = 1; o < 8; o <<= 1) {
            int u = __shfl_up_sync(0xffu, pw, o);
            if (t >= o) pw += u;
        }
        warp_s[t] = pw - ws;
    }
    __syncthreads();
    int ex = ps - s + warp_s[wid];
    int run = ex;
    if (base + 0 < NN) g_offs[base + 0] = run; run += v0;
    if (base + 1 < NN) g_offs[base + 1] = run; run += v1;
    if (base + 2 < NN) g_offs[base + 2] = run; run += v2;
    if (base + 3 < NN) g_offs[base + 3] = run;
    if (t == 255) g_bsum[b] = ex + s;
}

__global__ void k_scan2() {
    __shared__ int sh[4];
    int t = threadIdx.x;
    int v = (t < 98) ? g_bsum[t] : 0;
    int lane = t & 31, wid = t >> 5;
    int ps = v;
#pragma unroll
    for (int o = 1; o < 32; o <<= 1) {
        int u = __shfl_up_sync(0xffffffffu, ps, o);
        if (lane >= o) ps += u;
    }
    if (lane == 31) sh[wid] = ps;
    __syncthreads();
    if (t < 4) {
        int ws = sh[t];
        int pw = ws;
#pragma unroll
        for (int o = 1; o < 4; o <<= 1) {
            int u = __shfl_up_sync(0xfu, pw, o);
            if (t >= o) pw += u;
        }
        sh[t] = pw - ws;
    }
    __syncthreads();
    if (t < 98) g_bsum[t] = ps - v + sh[wid];
}

__global__ void k_scan3() {
    int i = blockIdx.x * blockDim.x + threadIdx.x;
    if (i < NN) {
        int o = g_offs[i] + g_bsum[i >> 10];
        g_offs[i] = o;
        g_fill[i] = o;
    }
    if (i == 0) g_offs[NN] = NE;
}

// ---------------- K5: build CSR (row, norm) per target node ---------------
__global__ void k_build(const int* __restrict__ ei, const float* __restrict__ w) {
    int e = blockIdx.x * blockDim.x + threadIdx.x;
    if (e >= NE) return;
    int row = ei[e];
    int col = ei[NE + e];
    float nm = g_dinv[row] * w[e] * g_dinv[col];
    int pos = atomicAdd(&g_fill[col], 1);
    g_csr[pos] = make_float2(__int_as_float(row), nm);
}

// ---------------- K6: aggX[n] = s*x[n] + sum nrm*x[row]  (gather) ---------
__global__ void k_aggX(const float* __restrict__ x) {
    int n = blockIdx.x * blockDim.x + threadIdx.x;
    if (n >= NN) return;
    float di = g_dinv[n];
    float s = di * di;
    float a0 = s * x[3 * n + 0];
    float a1 = s * x[3 * n + 1];
    float a2 = s * x[3 * n + 2];
    int beg = g_offs[n], end = g_offs[n + 1];
    for (int j = beg; j < end; j++) {
        float2 c = g_csr[j];
        int r = __float_as_int(c.x);
        float nm = c.y;
        a0 = fmaf(nm, x[3 * r + 0], a0);
        a1 = fmaf(nm, x[3 * r + 1], a1);
        a2 = fmaf(nm, x[3 * r + 2], a2);
    }
    g_aggX[3 * n + 0] = a0;
    g_aggX[3 * n + 1] = a1;
    g_aggX[3 * n + 2] = a2;
}

// ---------------- K7: h1 = silu(aggX @ W1 + b1) ---------------------------
__global__ void k_h1(const float* __restrict__ W1, const float* __restrict__ b1) {
    __shared__ float sW[4 * F1];
    for (int t = threadIdx.x; t < 4 * F1; t += blockDim.x)
        sW[t] = (t < 3 * F1) ? W1[t] : b1[t - 3 * F1];
    __syncthreads();
    int idx = blockIdx.x * blockDim.x + threadIdx.x;
    if (idx >= NN * 25) return;
    int n = idx / 25, c4 = idx % 25;
    float a0 = g_aggX[3 * n + 0];
    float a1 = g_aggX[3 * n + 1];
    float a2 = g_aggX[3 * n + 2];
#pragma unroll
    for (int j = 0; j < 4; j++) {
        int c = c4 * 4 + j;
        float v = fmaf(a0, sW[c], fmaf(a1, sW[F1 + c], fmaf(a2, sW[2 * F1 + c], sW[3 * F1 + c])));
        g_h1[n * F1 + c] = silu(v);
    }
}

// ---------------- K8: agg1[n] = s*h1[n] + sum nrm*h1[row] (warp/node) -----
__global__ void k_agg1() {
    int n = (blockIdx.x * blockDim.x + threadIdx.x) >> 5;
    int lane = threadIdx.x & 31;
    if (n >= NN) return;
    bool act = lane < 25;
    int beg = g_offs[n], end = g_offs[n + 1];
    float di = g_dinv[n];
    float s = di * di;
    float4 acc = make_float4(0.f, 0.f, 0.f, 0.f);
    if (act) {
        float4 h = *(const float4*)(g_h1 + (long)n * F1 + lane * 4);
        acc.x = s * h.x; acc.y = s * h.y; acc.z = s * h.z; acc.w = s * h.w;
    }
    int j = beg;
    for (; j + 2 <= end; j += 2) {
        float2 c0 = g_csr[j];
        float2 c1 = g_csr[j + 1];
        int r0 = __float_as_int(c0.x);
        int r1 = __float_as_int(c1.x);
        if (act) {
            float4 h0 = *(const float4*)(g_h1 + (long)r0 * F1 + lane * 4);
            float4 h1v = *(const float4*)(g_h1 + (long)r1 * F1 + lane * 4);
            acc.x = fmaf(c0.y, h0.x, acc.x); acc.y = fmaf(c0.y, h0.y, acc.y);
            acc.z = fmaf(c0.y, h0.z, acc.z); acc.w = fmaf(c0.y, h0.w, acc.w);
            acc.x = fmaf(c1.y, h1v.x, acc.x); acc.y = fmaf(c1.y, h1v.y, acc.y);
            acc.z = fmaf(c1.y, h1v.z, acc.z); acc.w = fmaf(c1.y, h1v.w, acc.w);
        }
    }
    if (j < end) {
        float2 c0 = g_csr[j];
        int r0 = __float_as_int(c0.x);
        if (act) {
            float4 h0 = *(const float4*)(g_h1 + (long)r0 * F1 + lane * 4);
            acc.x = fmaf(c0.y, h0.x, acc.x); acc.y = fmaf(c0.y, h0.y, acc.y);
            acc.z = fmaf(c0.y, h0.z, acc.z); acc.w = fmaf(c0.y, h0.w, acc.w);
        }
    }
    if (act)
        *(float4*)(g_agg1 + (long)n * F1 + lane * 4) = acc;
}

// ---------------- K9: 3xTF32 tensor-core GEMM + silu + fused mean-pool ----
// BM=64 nodes, BN=40 cols, 128 threads (4 warps, one m16 band each).
// K=100 padded to 104 (13 k8 steps). A smem row stride 108 -> conflict-free
// fragment LDS ((r*12+c) mod 32 distinct). Operands kept fp32 in smem;
// hi/lo tf32 split at fragment-load; acc += ahi*blo + alo*bhi + ahi*bhi.
#define BM 64
#define BN 40
#define KP 104
#define ASTRIDE 108

__global__ void k_gemm2(const float* __restrict__ W2, const float* __restrict__ b2,
                        const int* __restrict__ batch) {
    __shared__ float As[BM * ASTRIDE];   // [m][k] fp32; reused as sOut
    __shared__ float Bs[KP * BN];        // [k][c] fp32
    __shared__ int sBatch[BM];
    int tid = threadIdx.x;
    int lane = tid & 31;
    int wid = tid >> 5;
    int n0 = blockIdx.x * BM;
    int cb = blockIdx.y * BN;

    // load A tile (coalesced along k)
    for (int t = tid; t < BM * 25; t += 128) {
        int m = t / 25, k4 = t % 25;
        int n = n0 + m;
        float4 v = make_float4(0.f, 0.f, 0.f, 0.f);
        if (n < NN) v = *(const float4*)(g_agg1 + (long)n * F1 + k4 * 4);
        *(float4*)(As + m * ASTRIDE + k4 * 4) = v;
    }
    // zero K padding of A (cols 100..107)
    for (int t = tid; t < BM * 8; t += 128)
        As[(t / 8) * ASTRIDE + 100 + (t % 8)] = 0.f;
    // load B tile
    for (int t = tid; t < F1 * 10; t += 128) {
        int k = t / 10, c4 = t % 10;
        *(float4*)(Bs + k * BN + c4 * 4) = *(const float4*)(W2 + k * F2 + cb + c4 * 4);
    }
    // zero K padding of B (rows 100..103)
    for (int t = tid; t < 4 * BN; t += 128)
        Bs[(100 + t / BN) * BN + (t % BN)] = 0.f;
    if (tid < BM) {
        int n = n0 + tid;
        sBatch[tid] = (n < NN) ? batch[n] : -1;
    }
    __syncthreads();

    int base = wid * 16;
    int r = lane >> 2;
    int c = lane & 3;
    float acc[5][4] = {};

#pragma unroll
    for (int ks = 0; ks < 13; ks++) {
        int kb = ks * 8;
        float fa0 = As[(base + r) * ASTRIDE + kb + c];
        float fa1 = As[(base + r + 8) * ASTRIDE + kb + c];
        float fa2 = As[(base + r) * ASTRIDE + kb + c + 4];
        float fa3 = As[(base + r + 8) * ASTRIDE + kb + c + 4];
        unsigned ah0, al0, ah1, al1, ah2, al2, ah3, al3;
        split_tf32(fa0, ah0, al0);
        split_tf32(fa1, ah1, al1);
        split_tf32(fa2, ah2, al2);
        split_tf32(fa3, ah3, al3);
#pragma unroll
        for (int t = 0; t < 5; t++) {
            float fb0 = Bs[(kb + c) * BN + t * 8 + r];
            float fb1 = Bs[(kb + 4 + c) * BN + t * 8 + r];
            unsigned bh0, bl0, bh1, bl1;
            split_tf32(fb0, bh0, bl0);
            split_tf32(fb1, bh1, bl1);
            mma_tf32(acc[t][0], acc[t][1], acc[t][2], acc[t][3],
                     ah0, ah1, ah2, ah3, bl0, bl1);
            mma_tf32(acc[t][0], acc[t][1], acc[t][2], acc[t][3],
                     al0, al1, al2, al3, bh0, bh1);
            mma_tf32(acc[t][0], acc[t][1], acc[t][2], acc[t][3],
                     ah0, ah1, ah2, ah3, bh0, bh1);
        }
    }

    // epilogue: silu(acc+bias) -> smem; segmented pool -> g_sums
    __syncthreads();               // done reading As/Bs
    float* sOut = As;              // reuse: [BM][BN]
#pragma unroll
    for (int t = 0; t < 5; t++) {
        int col = t * 8 + c * 2;
        float bx = b2[cb + col];
        float by = b2[cb + col + 1];
        sOut[(base + r) * BN + col]         = silu(acc[t][0] + bx);
        sOut[(base + r) * BN + col + 1]     = silu(acc[t][1] + by);
        sOut[(base + r + 8) * BN + col]     = silu(acc[t][2] + bx);
        sOut[(base + r + 8) * BN + col + 1] = silu(acc[t][3] + by);
    }
    __syncthreads();

    if (tid < 120) {
        int cc = tid % BN;         // 0..39
        int seg = tid / BN;        // 0..2, rows seg*22 .. +22 (last 20)
        int mend = min(seg * 22 + 22, BM);
        float pacc = 0.f;
        int curg = -1;
        for (int m = seg * 22; m < mend; m++) {
            int g = sBatch[m];
            if (g != curg) {
                if (curg >= 0) atomicAdd(&g_sums[curg * F2 + cb + cc], pacc);
                curg = g;
                pacc = 0.f;
            }
            if (g >= 0) pacc += sOut[m * BN + cc];
        }
        if (curg >= 0) atomicAdd(&g_sums[curg * F2 + cb + cc], pacc);
    }
}

// ---------------- K10: head: silu(pooled@Wl1+bl1)@Wl2+bl2 -----------------
__global__ void k_head(const float* __restrict__ Wl1, const float* __restrict__ bl1,
                       const float* __restrict__ Wl2, const float* __restrict__ bl2,
                       float* __restrict__ out) {
    __shared__ float sp[F2];
    __shared__ float sh[F1];
    int g = blockIdx.x;
    int tid = threadIdx.x;
    float cnt = fmaxf(g_cnt[g], 1.0f);
    for (int c = tid; c < F2; c += blockDim.x)
        sp[c] = g_sums[g * F2 + c] / cnt;
    __syncthreads();
    if (tid < F1) {
        float acc = bl1[tid];
        for (int c = 0; c < F2; c++)
            acc = fmaf(sp[c], Wl1[c * F1 + tid], acc);
        sh[tid] = silu(acc);
    }
    __syncthreads();
    if (tid == 0) {
        float s = bl2[0];
        for (int j = 0; j < F1; j++)
            s = fmaf(sh[j], Wl2[j], s);
        out[g] = s;
    }
}

// ---------------- launch ---------------------------------------------------
extern "C" void kernel_launch(void* const* d_in, const int* in_sizes, int n_in,
                              void* d_out, int out_size) {
    const float* x   = (const float*)d_in[0];
    const float* ea  = (const float*)d_in[1];
    const float* W1  = (const float*)d_in[2];
    const float* b1  = (const float*)d_in[3];
    const float* W2  = (const float*)d_in[4];
    const float* b2  = (const float*)d_in[5];
    const float* Wl1 = (const float*)d_in[6];
    const float* bl1 = (const float*)d_in[7];
    const float* Wl2 = (const float*)d_in[8];
    const float* bl2 = (const float*)d_in[9];
    const int*   ei  = (const int*)d_in[10];
    const int*   bat = (const int*)d_in[11];
    float* out = (float*)d_out;

    k_init<<<(NN + 255) / 256, 256>>>();
    k_deg<<<(NE + 255) / 256, 256>>>(ei, ea);
    k_dinv<<<(NN + 255) / 256, 256>>>(bat);
    k_scan1<<<98, 256>>>();
    k_scan2<<<1, 128>>>();
    k_scan3<<<(NN + 255) / 256, 256>>>();
    k_build<<<(NE + 255) / 256, 256>>>(ei, ea);
    k_aggX<<<(NN + 255) / 256, 256>>>(x);
    k_h1<<<(NN * 25 + 255) / 256, 256>>>(W1, b1);
    k_agg1<<<(NN * 32 + 255) / 256, 256>>>();
    k_gemm2<<<dim3((NN + BM - 1) / BM, F2 / BN), 128>>>(W2, b2, bat);
    k_head<<<NG, 128>>>(Wl1, bl1, Wl2, bl2, out);
}

// round 6
// speedup vs baseline: 2.1792x; 1.0423x over previous
#include <cuda_runtime.h>
#include <math.h>

#define NN 100000
#define NE 1600000
#define NG 64
#define F1 100
#define F2 200

// ---------------- scratch (static device globals; no allocation) ----------
__device__ float2 g_pack[NN];          // (deg_sum, deg_count) packed for v2 red
__device__ float  g_dinv[NN];          // rsqrt(deg)
__device__ int    g_cdeg[NN];          // in-degree counts (for CSR)
__device__ int    g_offs[NN + 1];      // CSR offsets
__device__ int    g_fill[NN];          // CSR fill cursors
__device__ int    g_bsum[128];         // scan block sums
__device__ float2 g_csr[NE];           // (row as int bits, norm)
__device__ float  g_aggX[NN * 3];      // A_norm @ x
__device__ float  g_h1[NN * F1];       // silu(aggX @ W1 + b1)
__device__ float  g_agg1[NN * F1];     // A_norm @ h1
__device__ float  g_sums[NG * F2];     // pooled sums
__device__ float  g_cnt[NG];           // pooled counts

__device__ __forceinline__ float silu(float v) {
    return v / (1.0f + __expf(-v));
}

__device__ __forceinline__ unsigned f2tf32(float v) {
    unsigned r;
    asm("cvt.rna.tf32.f32 %0, %1;" : "=r"(r) : "f"(v));
    return r;
}

__device__ __forceinline__ void split_tf32(float v, unsigned& hi, unsigned& lo) {
    hi = f2tf32(v);
    lo = f2tf32(v - __uint_as_float(hi));
}

__device__ __forceinline__ void mma_tf32(float& d0, float& d1, float& d2, float& d3,
                                         unsigned a0, unsigned a1, unsigned a2, unsigned a3,
                                         unsigned b0, unsigned b1) {
    asm volatile("mma.sync.aligned.m16n8k8.row.col.f32.tf32.tf32.f32 "
                 "{%0,%1,%2,%3}, {%4,%5,%6,%7}, {%8,%9}, {%0,%1,%2,%3};"
                 : "+f"(d0), "+f"(d1), "+f"(d2), "+f"(d3)
                 : "r"(a0), "r"(a1), "r"(a2), "r"(a3), "r"(b0), "r"(b1));
}

__device__ __forceinline__ void red_add_v2(float2* p, float a, float b) {
    asm volatile("red.global.add.v2.f32 [%0], {%1,%2};"
                 :: "l"(p), "f"(a), "f"(b) : "memory");
}

// ---------------- K1: init pack (self-loop: deg=1, cnt=0), zero pooled ----
__global__ void k_init() {
    int i = blockIdx.x * blockDim.x + threadIdx.x;
    if (i < NN) g_pack[i] = make_float2(1.0f, 0.0f);
    if (i < NG * F2) g_sums[i] = 0.0f;
    if (i < NG) g_cnt[i] = 0.0f;
}

// ---------------- K2: packed deg/count reduction (1 atomic per edge) ------
__global__ void k_deg(const int* __restrict__ ei, const float* __restrict__ w) {
    int e = blockIdx.x * blockDim.x + threadIdx.x;
    if (e >= NE) return;
    int col = ei[NE + e];
    red_add_v2(&g_pack[col], w[e], 1.0f);
}

// ---------------- K3: dinv = rsqrt(deg); cdeg; graph counts ---------------
__global__ void k_dinv(const int* __restrict__ batch) {
    int n = blockIdx.x * blockDim.x + threadIdx.x;
    bool valid = n < NN;
    if (valid) {
        float2 p = g_pack[n];
        g_dinv[n] = rsqrtf(p.x);          // deg >= 1 (self loop)
        g_cdeg[n] = (int)p.y;             // counts exact in float
    }
    int g = valid ? batch[n] : -1;
    unsigned m = __match_any_sync(0xffffffffu, g);
    int lane = threadIdx.x & 31;
    int leader = __ffs(m) - 1;
    if (valid && lane == leader)
        atomicAdd(&g_cnt[g], (float)__popc(m));
}

// ---------------- scan: exclusive prefix sum of cdeg -> offs --------------
__global__ void k_scan1() {
    __shared__ int warp_s[8];
    int b = blockIdx.x, t = threadIdx.x;
    int base = b * 1024 + t * 4;
    int v0 = 0, v1 = 0, v2 = 0, v3 = 0;
    if (base + 0 < NN) v0 = g_cdeg[base + 0];
    if (base + 1 < NN) v1 = g_cdeg[base + 1];
    if (base + 2 < NN) v2 = g_cdeg[base + 2];
    if (base + 3 < NN) v3 = g_cdeg[base + 3];
    int s = v0 + v1 + v2 + v3;
    int lane = t & 31, wid = t >> 5;
    int ps = s;
#pragma unroll
    for (int o = 1; o < 32; o <<= 1) {
        int u = __shfl_up_sync(0xffffffffu, ps, o);
        if (lane >= o) ps += u;
    }
    if (lane == 31) warp_s[wid] = ps;
    __syncthreads();
    if (t < 8) {
        int ws = warp_s[t];
        int pw = ws;
#pragma unroll
        for (int o = 1; o < 8; o <<= 1) {
            int u = __shfl_up_sync(0xffu, pw, o);
            if (t >= o) pw += u;
        }
        warp_s[t] = pw - ws;
    }
    __syncthreads();
    int ex = ps - s + warp_s[wid];
    int run = ex;
    if (base + 0 < NN) g_offs[base + 0] = run; run += v0;
    if (base + 1 < NN) g_offs[base + 1] = run; run += v1;
    if (base + 2 < NN) g_offs[base + 2] = run; run += v2;
    if (base + 3 < NN) g_offs[base + 3] = run;
    if (t == 255) g_bsum[b] = ex + s;
}

__global__ void k_scan2() {
    __shared__ int sh[4];
    int t = threadIdx.x;
    int v = (t < 98) ? g_bsum[t] : 0;
    int lane = t & 31, wid = t >> 5;
    int ps = v;
#pragma unroll
    for (int o = 1; o < 32; o <<= 1) {
        int u = __shfl_up_sync(0xffffffffu, ps, o);
        if (lane >= o) ps += u;
    }
    if (lane == 31) sh[wid] = ps;
    __syncthreads();
    if (t < 4) {
        int ws = sh[t];
        int pw = ws;
#pragma unroll
        for (int o = 1; o < 4; o <<= 1) {
            int u = __shfl_up_sync(0xfu, pw, o);
            if (t >= o) pw += u;
        }
        sh[t] = pw - ws;
    }
    __syncthreads();
    if (t < 98) g_bsum[t] = ps - v + sh[wid];
}

__global__ void k_scan3() {
    int i = blockIdx.x * blockDim.x + threadIdx.x;
    if (i < NN) {
        int o = g_offs[i] + g_bsum[i >> 10];
        g_offs[i] = o;
        g_fill[i] = o;
    }
    if (i == 0) g_offs[NN] = NE;
}

// ---------------- K5: build CSR (row, norm) per target node ---------------
__global__ void k_build(const int* __restrict__ ei, const float* __restrict__ w) {
    int e = blockIdx.x * blockDim.x + threadIdx.x;
    if (e >= NE) return;
    int row = ei[e];
    int col = ei[NE + e];
    float nm = g_dinv[row] * w[e] * g_dinv[col];
    int pos = atomicAdd(&g_fill[col], 1);
    g_csr[pos] = make_float2(__int_as_float(row), nm);
}

// ---------------- K6: aggX[n] = s*x[n] + sum nrm*x[row]  (gather, MLP4) ---
__global__ void k_aggX(const float* __restrict__ x) {
    int n = blockIdx.x * blockDim.x + threadIdx.x;
    if (n >= NN) return;
    float di = g_dinv[n];
    float s = di * di;
    float a0 = s * x[3 * n + 0];
    float a1 = s * x[3 * n + 1];
    float a2 = s * x[3 * n + 2];
    int beg = g_offs[n], end = g_offs[n + 1];
    int j = beg;
    for (; j + 4 <= end; j += 4) {
        float2 c0 = g_csr[j + 0];
        float2 c1 = g_csr[j + 1];
        float2 c2 = g_csr[j + 2];
        float2 c3 = g_csr[j + 3];
        int r0 = __float_as_int(c0.x);
        int r1 = __float_as_int(c1.x);
        int r2 = __float_as_int(c2.x);
        int r3 = __float_as_int(c3.x);
        float x00 = x[3 * r0 + 0], x01 = x[3 * r0 + 1], x02 = x[3 * r0 + 2];
        float x10 = x[3 * r1 + 0], x11 = x[3 * r1 + 1], x12 = x[3 * r1 + 2];
        float x20 = x[3 * r2 + 0], x21 = x[3 * r2 + 1], x22 = x[3 * r2 + 2];
        float x30 = x[3 * r3 + 0], x31 = x[3 * r3 + 1], x32 = x[3 * r3 + 2];
        a0 = fmaf(c0.y, x00, a0); a1 = fmaf(c0.y, x01, a1); a2 = fmaf(c0.y, x02, a2);
        a0 = fmaf(c1.y, x10, a0); a1 = fmaf(c1.y, x11, a1); a2 = fmaf(c1.y, x12, a2);
        a0 = fmaf(c2.y, x20, a0); a1 = fmaf(c2.y, x21, a1); a2 = fmaf(c2.y, x22, a2);
        a0 = fmaf(c3.y, x30, a0); a1 = fmaf(c3.y, x31, a1); a2 = fmaf(c3.y, x32, a2);
    }
    for (; j < end; j++) {
        float2 c = g_csr[j];
        int r = __float_as_int(c.x);
        a0 = fmaf(c.y, x[3 * r + 0], a0);
        a1 = fmaf(c.y, x[3 * r + 1], a1);
        a2 = fmaf(c.y, x[3 * r + 2], a2);
    }
    g_aggX[3 * n + 0] = a0;
    g_aggX[3 * n + 1] = a1;
    g_aggX[3 * n + 2] = a2;
}

// ---------------- K7: h1 = silu(aggX @ W1 + b1) ---------------------------
__global__ void k_h1(const float* __restrict__ W1, const float* __restrict__ b1) {
    __shared__ float sW[4 * F1];
    for (int t = threadIdx.x; t < 4 * F1; t += blockDim.x)
        sW[t] = (t < 3 * F1) ? W1[t] : b1[t - 3 * F1];
    __syncthreads();
    int idx = blockIdx.x * blockDim.x + threadIdx.x;
    if (idx >= NN * 25) return;
    int n = idx / 25, c4 = idx % 25;
    float a0 = g_aggX[3 * n + 0];
    float a1 = g_aggX[3 * n + 1];
    float a2 = g_aggX[3 * n + 2];
    float4 o;
#pragma unroll
    for (int j = 0; j < 4; j++) {
        int c = c4 * 4 + j;
        float v = fmaf(a0, sW[c], fmaf(a1, sW[F1 + c], fmaf(a2, sW[2 * F1 + c], sW[3 * F1 + c])));
        (&o.x)[j] = silu(v);
    }
    *(float4*)(g_h1 + (long)n * F1 + c4 * 4) = o;
}

// ---------------- K8: agg1[n] = s*h1[n] + sum nrm*h1[row] (warp/node) -----
__global__ void k_agg1() {
    int n = (blockIdx.x * blockDim.x + threadIdx.x) >> 5;
    int lane = threadIdx.x & 31;
    if (n >= NN) return;
    bool act = lane < 25;
    int beg = g_offs[n], end = g_offs[n + 1];
    float di = g_dinv[n];
    float s = di * di;
    float4 acc = make_float4(0.f, 0.f, 0.f, 0.f);
    if (act) {
        float4 h = *(const float4*)(g_h1 + (long)n * F1 + lane * 4);
        acc.x = s * h.x; acc.y = s * h.y; acc.z = s * h.z; acc.w = s * h.w;
    }
    int j = beg;
    for (; j + 4 <= end; j += 4) {
        float2 c0 = g_csr[j + 0];
        float2 c1 = g_csr[j + 1];
        float2 c2 = g_csr[j + 2];
        float2 c3 = g_csr[j + 3];
        int r0 = __float_as_int(c0.x);
        int r1 = __float_as_int(c1.x);
        int r2 = __float_as_int(c2.x);
        int r3 = __float_as_int(c3.x);
        if (act) {
            float4 h0 = *(const float4*)(g_h1 + (long)r0 * F1 + lane * 4);
            float4 h1v = *(const float4*)(g_h1 + (long)r1 * F1 + lane * 4);
            float4 h2 = *(const float4*)(g_h1 + (long)r2 * F1 + lane * 4);
            float4 h3 = *(const float4*)(g_h1 + (long)r3 * F1 + lane * 4);
            acc.x = fmaf(c0.y, h0.x, acc.x); acc.y = fmaf(c0.y, h0.y, acc.y);
            acc.z = fmaf(c0.y, h0.z, acc.z); acc.w = fmaf(c0.y, h0.w, acc.w);
            acc.x = fmaf(c1.y, h1v.x, acc.x); acc.y = fmaf(c1.y, h1v.y, acc.y);
            acc.z = fmaf(c1.y, h1v.z, acc.z); acc.w = fmaf(c1.y, h1v.w, acc.w);
            acc.x = fmaf(c2.y, h2.x, acc.x); acc.y = fmaf(c2.y, h2.y, acc.y);
            acc.z = fmaf(c2.y, h2.z, acc.z); acc.w = fmaf(c2.y, h2.w, acc.w);
            acc.x = fmaf(c3.y, h3.x, acc.x); acc.y = fmaf(c3.y, h3.y, acc.y);
            acc.z = fmaf(c3.y, h3.z, acc.z); acc.w = fmaf(c3.y, h3.w, acc.w);
        }
    }
    for (; j < end; j++) {
        float2 c0 = g_csr[j];
        int r0 = __float_as_int(c0.x);
        if (act) {
            float4 h0 = *(const float4*)(g_h1 + (long)r0 * F1 + lane * 4);
            acc.x = fmaf(c0.y, h0.x, acc.x); acc.y = fmaf(c0.y, h0.y, acc.y);
            acc.z = fmaf(c0.y, h0.z, acc.z); acc.w = fmaf(c0.y, h0.w, acc.w);
        }
    }
    if (act)
        *(float4*)(g_agg1 + (long)n * F1 + lane * 4) = acc;
}

// ---------------- K9: 3xTF32 tensor-core GEMM + silu + fused mean-pool ----
#define BM 64
#define BN 40
#define KP 104
#define ASTRIDE 108

__global__ void k_gemm2(const float* __restrict__ W2, const float* __restrict__ b2,
                        const int* __restrict__ batch) {
    __shared__ float As[BM * ASTRIDE];   // [m][k] fp32; reused as sOut
    __shared__ float Bs[KP * BN];        // [k][c] fp32
    __shared__ int sBatch[BM];
    int tid = threadIdx.x;
    int lane = tid & 31;
    int wid = tid >> 5;
    int n0 = blockIdx.x * BM;
    int cb = blockIdx.y * BN;

    for (int t = tid; t < BM * 25; t += 128) {
        int m = t / 25, k4 = t % 25;
        int n = n0 + m;
        float4 v = make_float4(0.f, 0.f, 0.f, 0.f);
        if (n < NN) v = *(const float4*)(g_agg1 + (long)n * F1 + k4 * 4);
        *(float4*)(As + m * ASTRIDE + k4 * 4) = v;
    }
    for (int t = tid; t < BM * 8; t += 128)
        As[(t / 8) * ASTRIDE + 100 + (t % 8)] = 0.f;
    for (int t = tid; t < F1 * 10; t += 128) {
        int k = t / 10, c4 = t % 10;
        *(float4*)(Bs + k * BN + c4 * 4) = *(const float4*)(W2 + k * F2 + cb + c4 * 4);
    }
    for (int t = tid; t < 4 * BN; t += 128)
        Bs[(100 + t / BN) * BN + (t % BN)] = 0.f;
    if (tid < BM) {
        int n = n0 + tid;
        sBatch[tid] = (n < NN) ? batch[n] : -1;
    }
    __syncthreads();

    int base = wid * 16;
    int r = lane >> 2;
    int c = lane & 3;
    float acc[5][4] = {};

#pragma unroll
    for (int ks = 0; ks < 13; ks++) {
        int kb = ks * 8;
        float fa0 = As[(base + r) * ASTRIDE + kb + c];
        float fa1 = As[(base + r + 8) * ASTRIDE + kb + c];
        float fa2 = As[(base + r) * ASTRIDE + kb + c + 4];
        float fa3 = As[(base + r + 8) * ASTRIDE + kb + c + 4];
        unsigned ah0, al0, ah1, al1, ah2, al2, ah3, al3;
        split_tf32(fa0, ah0, al0);
        split_tf32(fa1, ah1, al1);
        split_tf32(fa2, ah2, al2);
        split_tf32(fa3, ah3, al3);
#pragma unroll
        for (int t = 0; t < 5; t++) {
            float fb0 = Bs[(kb + c) * BN + t * 8 + r];
            float fb1 = Bs[(kb + 4 + c) * BN + t * 8 + r];
            unsigned bh0, bl0, bh1, bl1;
            split_tf32(fb0, bh0, bl0);
            split_tf32(fb1, bh1, bl1);
            mma_tf32(acc[t][0], acc[t][1], acc[t][2], acc[t][3],
                     ah0, ah1, ah2, ah3, bl0, bl1);
            mma_tf32(acc[t][0], acc[t][1], acc[t][2], acc[t][3],
                     al0, al1, al2, al3, bh0, bh1);
            mma_tf32(acc[t][0], acc[t][1], acc[t][2], acc[t][3],
                     ah0, ah1, ah2, ah3, bh0, bh1);
        }
    }

    __syncthreads();               // done reading As/Bs
    float* sOut = As;              // reuse: [BM][BN]
#pragma unroll
    for (int t = 0; t < 5; t++) {
        int col = t * 8 + c * 2;
        float bx = b2[cb + col];
        float by = b2[cb + col + 1];
        sOut[(base + r) * BN + col]         = silu(acc[t][0] + bx);
        sOut[(base + r) * BN + col + 1]     = silu(acc[t][1] + by);
        sOut[(base + r + 8) * BN + col]     = silu(acc[t][2] + bx);
        sOut[(base + r + 8) * BN + col + 1] = silu(acc[t][3] + by);
    }
    __syncthreads();

    if (tid < 120) {
        int cc = tid % BN;
        int seg = tid / BN;
        int mend = min(seg * 22 + 22, BM);
        float pacc = 0.f;
        int curg = -1;
        for (int m = seg * 22; m < mend; m++) {
            int g = sBatch[m];
            if (g != curg) {
                if (curg >= 0) atomicAdd(&g_sums[curg * F2 + cb + cc], pacc);
                curg = g;
                pacc = 0.f;
            }
            if (g >= 0) pacc += sOut[m * BN + cc];
        }
        if (curg >= 0) atomicAdd(&g_sums[curg * F2 + cb + cc], pacc);
    }
}

// ---------------- K10: head: silu(pooled@Wl1+bl1)@Wl2+bl2 -----------------
__global__ void k_head(const float* __restrict__ Wl1, const float* __restrict__ bl1,
                       const float* __restrict__ Wl2, const float* __restrict__ bl2,
                       float* __restrict__ out) {
    __shared__ float sp[F2];
    __shared__ float sh[F1];
    int g = blockIdx.x;
    int tid = threadIdx.x;
    float cnt = fmaxf(g_cnt[g], 1.0f);
    for (int c = tid; c < F2; c += blockDim.x)
        sp[c] = g_sums[g * F2 + c] / cnt;
    __syncthreads();
    if (tid < F1) {
        float acc = bl1[tid];
        for (int c = 0; c < F2; c++)
            acc = fmaf(sp[c], Wl1[c * F1 + tid], acc);
        sh[tid] = silu(acc);
    }
    __syncthreads();
    if (tid == 0) {
        float s = bl2[0];
        for (int j = 0; j < F1; j++)
            s = fmaf(sh[j], Wl2[j], s);
        out[g] = s;
    }
}

// ---------------- launch ---------------------------------------------------
extern "C" void kernel_launch(void* const* d_in, const int* in_sizes, int n_in,
                              void* d_out, int out_size) {
    const float* x   = (const float*)d_in[0];
    const float* ea  = (const float*)d_in[1];
    const float* W1  = (const float*)d_in[2];
    const float* b1  = (const float*)d_in[3];
    const float* W2  = (const float*)d_in[4];
    const float* b2  = (const float*)d_in[5];
    const float* Wl1 = (const float*)d_in[6];
    const float* bl1 = (const float*)d_in[7];
    const float* Wl2 = (const float*)d_in[8];
    const float* bl2 = (const float*)d_in[9];
    const int*   ei  = (const int*)d_in[10];
    const int*   bat = (const int*)d_in[11];
    float* out = (float*)d_out;

    k_init<<<(NN + 255) / 256, 256>>>();
    k_deg<<<(NE + 255) / 256, 256>>>(ei, ea);
    k_dinv<<<(NN + 255) / 256, 256>>>(bat);
    k_scan1<<<98, 256>>>();
    k_scan2<<<1, 128>>>();
    k_scan3<<<(NN + 255) / 256, 256>>>();
    k_build<<<(NE + 255) / 256, 256>>>(ei, ea);
    k_aggX<<<(NN + 255) / 256, 256>>>(x);
    k_h1<<<(NN * 25 + 255) / 256, 256>>>(W1, b1);
    k_agg1<<<(NN * 32 + 255) / 256, 256>>>();
    k_gemm2<<<dim3((NN + BM - 1) / BM, F2 / BN), 128>>>(W2, b2, bat);
    k_head<<<NG, 128>>>(Wl1, bl1, Wl2, bl2, out);
}

// round 7
// speedup vs baseline: 2.1799x; 1.0003x over previous
#include <cuda_runtime.h>
#include <math.h>

#define NN 100000
#define NE 1600000
#define NG 64
#define F1 100
#define F2 200

// ---------------- scratch (static device globals; no allocation) ----------
__device__ float2 g_pack[NN];          // (deg_sum, deg_count) packed for v2 red
__device__ float  g_dinv[NN];          // rsqrt(deg)
__device__ int    g_cdeg[NN];          // in-degree counts (for CSR)
__device__ int    g_offs[NN + 1];      // CSR offsets
__device__ int    g_fill[NN];          // CSR fill cursors
__device__ int    g_bsum[128];         // scan block sums
__device__ float2 g_csr[NE];           // (row as int bits, norm)
__device__ float  g_aggX[NN * 3];      // A_norm @ x
__device__ float  g_h1[NN * F1];       // silu(aggX @ W1 + b1)
__device__ float  g_agg1[NN * F1];     // A_norm @ h1
__device__ float  g_sums[NG * F2];     // pooled sums
__device__ float  g_cnt[NG];           // pooled counts

__device__ __forceinline__ float silu(float v) {
    return v / (1.0f + __expf(-v));
}

__device__ __forceinline__ unsigned f2tf32(float v) {
    unsigned r;
    asm("cvt.rna.tf32.f32 %0, %1;" : "=r"(r) : "f"(v));
    return r;
}

__device__ __forceinline__ void split_tf32(float v, unsigned& hi, unsigned& lo) {
    hi = f2tf32(v);
    lo = f2tf32(v - __uint_as_float(hi));
}

__device__ __forceinline__ void mma_tf32(float& d0, float& d1, float& d2, float& d3,
                                         unsigned a0, unsigned a1, unsigned a2, unsigned a3,
                                         unsigned b0, unsigned b1) {
    asm volatile("mma.sync.aligned.m16n8k8.row.col.f32.tf32.tf32.f32 "
                 "{%0,%1,%2,%3}, {%4,%5,%6,%7}, {%8,%9}, {%0,%1,%2,%3};"
                 : "+f"(d0), "+f"(d1), "+f"(d2), "+f"(d3)
                 : "r"(a0), "r"(a1), "r"(a2), "r"(a3), "r"(b0), "r"(b1));
}

__device__ __forceinline__ void red_add_v2(float2* p, float a, float b) {
    asm volatile("red.global.add.v2.f32 [%0], {%1,%2};"
                 :: "l"(p), "f"(a), "f"(b) : "memory");
}

// ---------------- K1: init pack (self-loop: deg=1, cnt=0), zero pooled ----
__global__ void k_init() {
    int i = blockIdx.x * blockDim.x + threadIdx.x;
    if (i < NN) g_pack[i] = make_float2(1.0f, 0.0f);
    if (i < NG * F2) g_sums[i] = 0.0f;
    if (i < NG) g_cnt[i] = 0.0f;
}

// ---------------- K2: packed deg/count reduction (1 atomic per edge) ------
__global__ void k_deg(const int* __restrict__ ei, const float* __restrict__ w) {
    int e = blockIdx.x * blockDim.x + threadIdx.x;
    if (e >= NE) return;
    int col = ei[NE + e];
    red_add_v2(&g_pack[col], w[e], 1.0f);
}

// ---------------- K3: dinv = rsqrt(deg); cdeg; graph counts ---------------
__global__ void k_dinv(const int* __restrict__ batch) {
    int n = blockIdx.x * blockDim.x + threadIdx.x;
    bool valid = n < NN;
    if (valid) {
        float2 p = g_pack[n];
        g_dinv[n] = rsqrtf(p.x);          // deg >= 1 (self loop)
        g_cdeg[n] = (int)p.y;             // counts exact in float
    }
    int g = valid ? batch[n] : -1;
    unsigned m = __match_any_sync(0xffffffffu, g);
    int lane = threadIdx.x & 31;
    int leader = __ffs(m) - 1;
    if (valid && lane == leader)
        atomicAdd(&g_cnt[g], (float)__popc(m));
}

// ---------------- scan: exclusive prefix sum of cdeg -> offs --------------
__global__ void k_scan1() {
    __shared__ int warp_s[8];
    int b = blockIdx.x, t = threadIdx.x;
    int base = b * 1024 + t * 4;
    int v0 = 0, v1 = 0, v2 = 0, v3 = 0;
    if (base + 0 < NN) v0 = g_cdeg[base + 0];
    if (base + 1 < NN) v1 = g_cdeg[base + 1];
    if (base + 2 < NN) v2 = g_cdeg[base + 2];
    if (base + 3 < NN) v3 = g_cdeg[base + 3];
    int s = v0 + v1 + v2 + v3;
    int lane = t & 31, wid = t >> 5;
    int ps = s;
#pragma unroll
    for (int o = 1; o < 32; o <<= 1) {
        int u = __shfl_up_sync(0xffffffffu, ps, o);
        if (lane >= o) ps += u;
    }
    if (lane == 31) warp_s[wid] = ps;
    __syncthreads();
    if (t < 8) {
        int ws = warp_s[t];
        int pw = ws;
#pragma unroll
        for (int o = 1; o < 8; o <<= 1) {
            int u = __shfl_up_sync(0xffu, pw, o);
            if (t >= o) pw += u;
        }
        warp_s[t] = pw - ws;
    }
    __syncthreads();
    int ex = ps - s + warp_s[wid];
    int run = ex;
    if (base + 0 < NN) g_offs[base + 0] = run; run += v0;
    if (base + 1 < NN) g_offs[base + 1] = run; run += v1;
    if (base + 2 < NN) g_offs[base + 2] = run; run += v2;
    if (base + 3 < NN) g_offs[base + 3] = run;
    if (t == 255) g_bsum[b] = ex + s;
}

__global__ void k_scan2() {
    __shared__ int sh[4];
    int t = threadIdx.x;
    int v = (t < 98) ? g_bsum[t] : 0;
    int lane = t & 31, wid = t >> 5;
    int ps = v;
#pragma unroll
    for (int o = 1; o < 32; o <<= 1) {
        int u = __shfl_up_sync(0xffffffffu, ps, o);
        if (lane >= o) ps += u;
    }
    if (lane == 31) sh[wid] = ps;
    __syncthreads();
    if (t < 4) {
        int ws = sh[t];
        int pw = ws;
#pragma unroll
        for (int o = 1; o < 4; o <<= 1) {
            int u = __shfl_up_sync(0xfu, pw, o);
            if (t >= o) pw += u;
        }
        sh[t] = pw - ws;
    }
    __syncthreads();
    if (t < 98) g_bsum[t] = ps - v + sh[wid];
}

__global__ void k_scan3() {
    int i = blockIdx.x * blockDim.x + threadIdx.x;
    if (i < NN) {
        int o = g_offs[i] + g_bsum[i >> 10];
        g_offs[i] = o;
        g_fill[i] = o;
    }
    if (i == 0) g_offs[NN] = NE;
}

// ---------------- K5: build CSR (row, norm) per target node ---------------
__global__ void k_build(const int* __restrict__ ei, const float* __restrict__ w) {
    int e = blockIdx.x * blockDim.x + threadIdx.x;
    if (e >= NE) return;
    int row = ei[e];
    int col = ei[NE + e];
    float nm = g_dinv[row] * w[e] * g_dinv[col];
    int pos = atomicAdd(&g_fill[col], 1);
    g_csr[pos] = make_float2(__int_as_float(row), nm);
}

// ---------------- K6: aggX[n] = s*x[n] + sum nrm*x[row]  (gather, MLP4) ---
__global__ void k_aggX(const float* __restrict__ x) {
    int n = blockIdx.x * blockDim.x + threadIdx.x;
    if (n >= NN) return;
    float di = g_dinv[n];
    float s = di * di;
    float a0 = s * x[3 * n + 0];
    float a1 = s * x[3 * n + 1];
    float a2 = s * x[3 * n + 2];
    int beg = g_offs[n], end = g_offs[n + 1];
    int j = beg;
    for (; j + 4 <= end; j += 4) {
        float2 c0 = g_csr[j + 0];
        float2 c1 = g_csr[j + 1];
        float2 c2 = g_csr[j + 2];
        float2 c3 = g_csr[j + 3];
        int r0 = __float_as_int(c0.x);
        int r1 = __float_as_int(c1.x);
        int r2 = __float_as_int(c2.x);
        int r3 = __float_as_int(c3.x);
        float x00 = x[3 * r0 + 0], x01 = x[3 * r0 + 1], x02 = x[3 * r0 + 2];
        float x10 = x[3 * r1 + 0], x11 = x[3 * r1 + 1], x12 = x[3 * r1 + 2];
        float x20 = x[3 * r2 + 0], x21 = x[3 * r2 + 1], x22 = x[3 * r2 + 2];
        float x30 = x[3 * r3 + 0], x31 = x[3 * r3 + 1], x32 = x[3 * r3 + 2];
        a0 = fmaf(c0.y, x00, a0); a1 = fmaf(c0.y, x01, a1); a2 = fmaf(c0.y, x02, a2);
        a0 = fmaf(c1.y, x10, a0); a1 = fmaf(c1.y, x11, a1); a2 = fmaf(c1.y, x12, a2);
        a0 = fmaf(c2.y, x20, a0); a1 = fmaf(c2.y, x21, a1); a2 = fmaf(c2.y, x22, a2);
        a0 = fmaf(c3.y, x30, a0); a1 = fmaf(c3.y, x31, a1); a2 = fmaf(c3.y, x32, a2);
    }
    for (; j < end; j++) {
        float2 c = g_csr[j];
        int r = __float_as_int(c.x);
        a0 = fmaf(c.y, x[3 * r + 0], a0);
        a1 = fmaf(c.y, x[3 * r + 1], a1);
        a2 = fmaf(c.y, x[3 * r + 2], a2);
    }
    g_aggX[3 * n + 0] = a0;
    g_aggX[3 * n + 1] = a1;
    g_aggX[3 * n + 2] = a2;
}

// ---------------- K7: h1 = silu(aggX @ W1 + b1) ---------------------------
__global__ void k_h1(const float* __restrict__ W1, const float* __restrict__ b1) {
    __shared__ float sW[4 * F1];
    for (int t = threadIdx.x; t < 4 * F1; t += blockDim.x)
        sW[t] = (t < 3 * F1) ? W1[t] : b1[t - 3 * F1];
    __syncthreads();
    int idx = blockIdx.x * blockDim.x + threadIdx.x;
    if (idx >= NN * 25) return;
    int n = idx / 25, c4 = idx % 25;
    float a0 = g_aggX[3 * n + 0];
    float a1 = g_aggX[3 * n + 1];
    float a2 = g_aggX[3 * n + 2];
    float4 o;
#pragma unroll
    for (int j = 0; j < 4; j++) {
        int c = c4 * 4 + j;
        float v = fmaf(a0, sW[c], fmaf(a1, sW[F1 + c], fmaf(a2, sW[2 * F1 + c], sW[3 * F1 + c])));
        (&o.x)[j] = silu(v);
    }
    *(float4*)(g_h1 + (long)n * F1 + c4 * 4) = o;
}

// ---------------- K8: agg1[n] = s*h1[n] + sum nrm*h1[row] (warp/node) -----
__global__ void k_agg1() {
    int n = (blockIdx.x * blockDim.x + threadIdx.x) >> 5;
    int lane = threadIdx.x & 31;
    if (n >= NN) return;
    bool act = lane < 25;
    int beg = g_offs[n], end = g_offs[n + 1];
    float di = g_dinv[n];
    float s = di * di;
    float4 acc = make_float4(0.f, 0.f, 0.f, 0.f);
    if (act) {
        float4 h = *(const float4*)(g_h1 + (long)n * F1 + lane * 4);
        acc.x = s * h.x; acc.y = s * h.y; acc.z = s * h.z; acc.w = s * h.w;
    }
    int j = beg;
    for (; j + 4 <= end; j += 4) {
        float2 c0 = g_csr[j + 0];
        float2 c1 = g_csr[j + 1];
        float2 c2 = g_csr[j + 2];
        float2 c3 = g_csr[j + 3];
        int r0 = __float_as_int(c0.x);
        int r1 = __float_as_int(c1.x);
        int r2 = __float_as_int(c2.x);
        int r3 = __float_as_int(c3.x);
        if (act) {
            float4 h0 = *(const float4*)(g_h1 + (long)r0 * F1 + lane * 4);
            float4 h1v = *(const float4*)(g_h1 + (long)r1 * F1 + lane * 4);
            float4 h2 = *(const float4*)(g_h1 + (long)r2 * F1 + lane * 4);
            float4 h3 = *(const float4*)(g_h1 + (long)r3 * F1 + lane * 4);
            acc.x = fmaf(c0.y, h0.x, acc.x); acc.y = fmaf(c0.y, h0.y, acc.y);
            acc.z = fmaf(c0.y, h0.z, acc.z); acc.w = fmaf(c0.y, h0.w, acc.w);
            acc.x = fmaf(c1.y, h1v.x, acc.x); acc.y = fmaf(c1.y, h1v.y, acc.y);
            acc.z = fmaf(c1.y, h1v.z, acc.z); acc.w = fmaf(c1.y, h1v.w, acc.w);
            acc.x = fmaf(c2.y, h2.x, acc.x); acc.y = fmaf(c2.y, h2.y, acc.y);
            acc.z = fmaf(c2.y, h2.z, acc.z); acc.w = fmaf(c2.y, h2.w, acc.w);
            acc.x = fmaf(c3.y, h3.x, acc.x); acc.y = fmaf(c3.y, h3.y, acc.y);
            acc.z = fmaf(c3.y, h3.z, acc.z); acc.w = fmaf(c3.y, h3.w, acc.w);
        }
    }
    for (; j < end; j++) {
        float2 c0 = g_csr[j];
        int r0 = __float_as_int(c0.x);
        if (act) {
            float4 h0 = *(const float4*)(g_h1 + (long)r0 * F1 + lane * 4);
            acc.x = fmaf(c0.y, h0.x, acc.x); acc.y = fmaf(c0.y, h0.y, acc.y);
            acc.z = fmaf(c0.y, h0.z, acc.z); acc.w = fmaf(c0.y, h0.w, acc.w);
        }
    }
    if (act)
        *(float4*)(g_agg1 + (long)n * F1 + lane * 4) = acc;
}

// ---------------- K9: 3xTF32 tensor-core GEMM + silu + fused mean-pool ----
#define BM 64
#define BN 40
#define KP 104
#define ASTRIDE 108

__global__ void k_gemm2(const float* __restrict__ W2, const float* __restrict__ b2,
                        const int* __restrict__ batch) {
    __shared__ float As[BM * ASTRIDE];   // [m][k] fp32; reused as sOut
    __shared__ float Bs[KP * BN];        // [k][c] fp32
    __shared__ int sBatch[BM];
    int tid = threadIdx.x;
    int lane = tid & 31;
    int wid = tid >> 5;
    int n0 = blockIdx.x * BM;
    int cb = blockIdx.y * BN;

    for (int t = tid; t < BM * 25; t += 128) {
        int m = t / 25, k4 = t % 25;
        int n = n0 + m;
        float4 v = make_float4(0.f, 0.f, 0.f, 0.f);
        if (n < NN) v = *(const float4*)(g_agg1 + (long)n * F1 + k4 * 4);
        *(float4*)(As + m * ASTRIDE + k4 * 4) = v;
    }
    for (int t = tid; t < BM * 8; t += 128)
        As[(t / 8) * ASTRIDE + 100 + (t % 8)] = 0.f;
    for (int t = tid; t < F1 * 10; t += 128) {
        int k = t / 10, c4 = t % 10;
        *(float4*)(Bs + k * BN + c4 * 4) = *(const float4*)(W2 + k * F2 + cb + c4 * 4);
    }
    for (int t = tid; t < 4 * BN; t += 128)
        Bs[(100 + t / BN) * BN + (t % BN)] = 0.f;
    if (tid < BM) {
        int n = n0 + tid;
        sBatch[tid] = (n < NN) ? batch[n] : -1;
    }
    __syncthreads();

    int base = wid * 16;
    int r = lane >> 2;
    int c = lane & 3;
    float acc[5][4] = {};

#pragma unroll
    for (int ks = 0; ks < 13; ks++) {
        int kb = ks * 8;
        float fa0 = As[(base + r) * ASTRIDE + kb + c];
        float fa1 = As[(base + r + 8) * ASTRIDE + kb + c];
        float fa2 = As[(base + r) * ASTRIDE + kb + c + 4];
        float fa3 = As[(base + r + 8) * ASTRIDE + kb + c + 4];
        unsigned ah0, al0, ah1, al1, ah2, al2, ah3, al3;
        split_tf32(fa0, ah0, al0);
        split_tf32(fa1, ah1, al1);
        split_tf32(fa2, ah2, al2);
        split_tf32(fa3, ah3, al3);
#pragma unroll
        for (int t = 0; t < 5; t++) {
            float fb0 = Bs[(kb + c) * BN + t * 8 + r];
            float fb1 = Bs[(kb + 4 + c) * BN + t * 8 + r];
            unsigned bh0, bl0, bh1, bl1;
            split_tf32(fb0, bh0, bl0);
            split_tf32(fb1, bh1, bl1);
            mma_tf32(acc[t][0], acc[t][1], acc[t][2], acc[t][3],
                     ah0, ah1, ah2, ah3, bl0, bl1);
            mma_tf32(acc[t][0], acc[t][1], acc[t][2], acc[t][3],
                     al0, al1, al2, al3, bh0, bh1);
            mma_tf32(acc[t][0], acc[t][1], acc[t][2], acc[t][3],
                     ah0, ah1, ah2, ah3, bh0, bh1);
        }
    }

    __syncthreads();               // done reading As/Bs
    float* sOut = As;              // reuse: [BM][BN]
#pragma unroll
    for (int t = 0; t < 5; t++) {
        int col = t * 8 + c * 2;
        float bx = b2[cb + col];
        float by = b2[cb + col + 1];
        sOut[(base + r) * BN + col]         = silu(acc[t][0] + bx);
        sOut[(base + r) * BN + col + 1]     = silu(acc[t][1] + by);
        sOut[(base + r + 8) * BN + col]     = silu(acc[t][2] + bx);
        sOut[(base + r + 8) * BN + col + 1] = silu(acc[t][3] + by);
    }
    __syncthreads();

    if (tid < 120) {
        int cc = tid % BN;
        int seg = tid / BN;
        int mend = min(seg * 22 + 22, BM);
        float pacc = 0.f;
        int curg = -1;
        for (int m = seg * 22; m < mend; m++) {
            int g = sBatch[m];
            if (g != curg) {
                if (curg >= 0) atomicAdd(&g_sums[curg * F2 + cb + cc], pacc);
                curg = g;
                pacc = 0.f;
            }
            if (g >= 0) pacc += sOut[m * BN + cc];
        }
        if (curg >= 0) atomicAdd(&g_sums[curg * F2 + cb + cc], pacc);
    }
}

// ---------------- K10: head: silu(pooled@Wl1+bl1)@Wl2+bl2 -----------------
__global__ void k_head(const float* __restrict__ Wl1, const float* __restrict__ bl1,
                       const float* __restrict__ Wl2, const float* __restrict__ bl2,
                       float* __restrict__ out) {
    __shared__ float sp[F2];
    __shared__ float sh[F1];
    int g = blockIdx.x;
    int tid = threadIdx.x;
    float cnt = fmaxf(g_cnt[g], 1.0f);
    for (int c = tid; c < F2; c += blockDim.x)
        sp[c] = g_sums[g * F2 + c] / cnt;
    __syncthreads();
    if (tid < F1) {
        float acc = bl1[tid];
        for (int c = 0; c < F2; c++)
            acc = fmaf(sp[c], Wl1[c * F1 + tid], acc);
        sh[tid] = silu(acc);
    }
    __syncthreads();
    if (tid == 0) {
        float s = bl2[0];
        for (int j = 0; j < F1; j++)
            s = fmaf(sh[j], Wl2[j], s);
        out[g] = s;
    }
}

// ---------------- launch ---------------------------------------------------
extern "C" void kernel_launch(void* const* d_in, const int* in_sizes, int n_in,
                              void* d_out, int out_size) {
    const float* x   = (const float*)d_in[0];
    const float* ea  = (const float*)d_in[1];
    const float* W1  = (const float*)d_in[2];
    const float* b1  = (const float*)d_in[3];
    const float* W2  = (const float*)d_in[4];
    const float* b2  = (const float*)d_in[5];
    const float* Wl1 = (const float*)d_in[6];
    const float* bl1 = (const float*)d_in[7];
    const float* Wl2 = (const float*)d_in[8];
    const float* bl2 = (const float*)d_in[9];
    const int*   ei  = (const int*)d_in[10];
    const int*   bat = (const int*)d_in[11];
    float* out = (float*)d_out;

    k_init<<<(NN + 255) / 256, 256>>>();
    k_deg<<<(NE + 255) / 256, 256>>>(ei, ea);
    k_dinv<<<(NN + 255) / 256, 256>>>(bat);
    k_scan1<<<98, 256>>>();
    k_scan2<<<1, 128>>>();
    k_scan3<<<(NN + 255) / 256, 256>>>();
    k_build<<<(NE + 255) / 256, 256>>>(ei, ea);
    k_aggX<<<(NN + 255) / 256, 256>>>(x);
    k_h1<<<(NN * 25 + 255) / 256, 256>>>(W1, b1);
    k_agg1<<<(NN * 32 + 255) / 256, 256>>>();
    k_gemm2<<<dim3((NN + BM - 1) / BM, F2 / BN), 128>>>(W2, b2, bat);
    k_head<<<NG, 128>>>(Wl1, bl1, Wl2, bl2, out);
}